// round 15
// baseline (speedup 1.0000x reference)
#include <cuda_runtime.h>
#include <cuda_bf16.h>
#include <cstdint>
#include <math.h>

// Problem constants
#define Bn 16
#define Nn 1024
#define En 16384
#define Dn 256
constexpr int ME = Bn * En;   // 262144 edge rows
constexpr int MN = Bn * Nn;   // 16384 node rows

// ============================ PTX helpers ===================================
__device__ __forceinline__ uint32_t smem_u32(const void* p) {
    uint32_t a;
    asm("{ .reg .u64 t; cvta.to.shared.u64 t, %1; cvt.u32.u64 %0, t; }"
        : "=r"(a) : "l"(p));
    return a;
}

#define LDSM4(r, addr) \
    asm volatile("ldmatrix.sync.aligned.m8n8.x4.shared.b16 {%0,%1,%2,%3}, [%4];" \
        : "=r"((r)[0]), "=r"((r)[1]), "=r"((r)[2]), "=r"((r)[3]) : "r"(addr))

#define MMA_BF16(d, a, b) \
    asm volatile("mma.sync.aligned.m16n8k16.row.col.f32.bf16.bf16.f32 " \
        "{%0,%1,%2,%3}, {%4,%5,%6,%7}, {%8,%9}, {%0,%1,%2,%3};" \
        : "+f"((d)[0]), "+f"((d)[1]), "+f"((d)[2]), "+f"((d)[3]) \
        : "r"((a)[0]), "r"((a)[1]), "r"((a)[2]), "r"((a)[3]), \
          "r"((b)[0]), "r"((b)[1]))

#define CP_ASYNC16(dst, src) \
    asm volatile("cp.async.cg.shared.global [%0], [%1], 16;" :: "r"(dst), "l"(src))
#define CP_COMMIT asm volatile("cp.async.commit_group;" ::: "memory")
#define CP_WAIT0  asm volatile("cp.async.wait_group 0;" ::: "memory")

#define RED_ADD_V2(p, a, b) \
    asm volatile("red.global.add.v2.f32 [%0], {%1,%2};" :: "l"(p), "f"(a), "f"(b) : "memory")

// Programmatic Dependent Launch (sm_90 PTX, valid on compute_103)
#define GDC_WAIT   asm volatile("griddepcontrol.wait;" ::: "memory")
#define GDC_LAUNCH asm volatile("griddepcontrol.launch_dependents;" ::: "memory")

#define SW128(x) ((x) ^ (((x) >> 3) & 0x70))

// ============================ scratch globals ================================
__device__ float g_buf1[(size_t)ME * Dn];   // hidden (bf16 hi/lo pair alias)
__device__ float g_msg [(size_t)ME * Dn];   // msg    (bf16 hi/lo pair alias)
__device__ float g_agg [(size_t)MN * Dn];   // fp32 (atomics)
__device__ float g_hn  [(size_t)MN * Dn];   // hn     (bf16 hi/lo pair alias)
__device__ float g_node[(size_t)MN * Dn];   // fp32 pre-LN
__device__ float g_p1  [(size_t)MN * Dn];   // node_feat @ W1a (fp32)
__device__ float g_p3  [(size_t)MN * Dn];   // node_feat @ W1c (fp32)
__device__ float g_nfs [(size_t)MN * Dn];   // node_feat pre-split (bf16 pair)
__device__ float g_cnt [MN];
__device__ float g_invc[MN];
__device__ int   g_srcrow[ME];
__device__ int   g_dstrow[ME];
__device__ float g_maskf [ME];
__device__ float g_nmaskf[MN];
__device__ float g_zero256[256];
// pre-transposed + bf16-split weights, 8 matrices of [256][256]
__device__ __nv_bfloat16 g_wth[524288];
__device__ __nv_bfloat16 g_wtl[524288];
constexpr size_t OW_T1A = 0,      OW_T1B = 65536,  OW_T1C = 131072,
                 OW_TW2 = 196608, OW_EW1 = 262144, OW_EW2 = 327680,
                 OW_NW1 = 393216, OW_NW2 = 458752;

__device__ __forceinline__ float silu_f(float x) { return x / (1.0f + __expf(-x)); }

// mask dtype: 0=float32, 1=uint8, 2=int32 (sniff first 16 words of buffer)
__device__ __forceinline__ int sniff_dt(const unsigned int* m) {
    bool big = false, up = false;
    #pragma unroll
    for (int i = 0; i < 16; i++) {
        unsigned int w = m[i];
        unsigned char b0 = w & 0xff, b1 = (w >> 8) & 0xff,
                      b2 = (w >> 16) & 0xff, b3 = (w >> 24) & 0xff;
        if (b0 >= 2 || b1 >= 2 || b2 >= 2 || b3 >= 2) big = true;
        if (b1 | b2 | b3) up = true;
    }
    return big ? 0 : (up ? 1 : 2);
}

__device__ __forceinline__ float read_mask(const void* p, int i, int dt) {
    if (dt == 0) return ((const float*)p)[i];
    if (dt == 1) return ((const unsigned char*)p)[i] ? 1.0f : 0.0f;
    return ((const int*)p)[i] ? 1.0f : 0.0f;
}

__device__ __forceinline__ void split_bf16x4(float4 v, uint2& hi, uint2& lo) {
    __nv_bfloat162 h01 = __floats2bfloat162_rn(v.x, v.y);
    __nv_bfloat162 h23 = __floats2bfloat162_rn(v.z, v.w);
    float2 f01 = __bfloat1622float2(h01);
    float2 f23 = __bfloat1622float2(h23);
    __nv_bfloat162 l01 = __floats2bfloat162_rn(v.x - f01.x, v.y - f01.y);
    __nv_bfloat162 l23 = __floats2bfloat162_rn(v.z - f23.x, v.w - f23.y);
    hi.x = *(uint32_t*)&h01; hi.y = *(uint32_t*)&h23;
    lo.x = *(uint32_t*)&l01; lo.y = *(uint32_t*)&l23;
}

// ---------------- small prep kernels ----------------------------------------
__global__ void prep_edges(const int* __restrict__ edge_index,
                           const void* __restrict__ edge_mask) {
    __shared__ int sdt;
    GDC_WAIT;
    GDC_LAUNCH;
    if (threadIdx.x == 0) sdt = sniff_dt((const unsigned int*)edge_mask);
    __syncthreads();
    int dt = sdt;
    int r = blockIdx.x * blockDim.x + threadIdx.x;
    if (r >= ME) return;
    int b = r >> 14;
    int e = r & (En - 1);
    int src = edge_index[(size_t)b * 2 * En + e];
    int dst = edge_index[(size_t)b * 2 * En + En + e];
    float m = (read_mask(edge_mask, r, dt) != 0.0f) ? 1.0f : 0.0f;
    g_srcrow[r] = b * Nn + src;
    g_dstrow[r] = b * Nn + dst;
    g_maskf[r]  = m;
    if (m != 0.0f) atomicAdd(&g_cnt[b * Nn + dst], 1.0f);
}

__global__ void prep_nodes(const void* __restrict__ node_mask,
                           const void* __restrict__ edge_mask) {
    __shared__ int sdt;
    GDC_WAIT;
    GDC_LAUNCH;
    if (threadIdx.x == 0) sdt = sniff_dt((const unsigned int*)edge_mask);
    __syncthreads();
    int dt = sdt;
    int v = blockIdx.x * blockDim.x + threadIdx.x;
    if (v >= MN) return;
    g_invc[v]   = 1.0f / fmaxf(g_cnt[v], 1.0f);
    g_nmaskf[v] = (read_mask(node_mask, v, dt) != 0.0f) ? 1.0f : 0.0f;
}

// elementwise fp32 -> bf16 hi/lo pair split (node_feat)
__global__ void split_pair(const float4* __restrict__ src,
                           uint2* __restrict__ dsth, uint2* __restrict__ dstl) {
    GDC_WAIT;
    GDC_LAUNCH;
    int i = blockIdx.x * blockDim.x + threadIdx.x;
    uint2 hi, lo;
    split_bf16x4(src[i], hi, lo);
    dsth[i] = hi;
    dstl[i] = lo;
}

// All 8 weight transposes in one launch; smem-tile coalesced.
struct WSrcs { const float* p[8]; };
__global__ void prep_weights_all(WSrcs srcs,
                                 __nv_bfloat16* __restrict__ wth,
                                 __nv_bfloat16* __restrict__ wtl) {
    __shared__ float tile[32][33];
    GDC_LAUNCH;
    const float* src = srcs.p[blockIdx.z];
    int kt = blockIdx.x * 32, nt = blockIdx.y * 32;
    #pragma unroll
    for (int i = threadIdx.y; i < 32; i += 8)
        tile[i][threadIdx.x] = src[(size_t)(kt + i) * 256 + nt + threadIdx.x];
    __syncthreads();
    size_t base = (size_t)blockIdx.z * 65536;
    #pragma unroll
    for (int i = threadIdx.y; i < 32; i += 8) {
        int n = nt + i, k = kt + threadIdx.x;
        float v = tile[threadIdx.x][i];
        __nv_bfloat16 h = __float2bfloat16_rn(v);
        wth[base + (size_t)n * 256 + k] = h;
        wtl[base + (size_t)n * 256 + k] = __float2bfloat16_rn(v - __bfloat162float(h));
    }
}

// ============================ tensor-core GEMM (mma.sync) ====================
// out[M,256] = A[M,256] @ W[256,256] via bf16x3 (AhiBhi + AloBhi + AhiBlo).
// Block tile 128x128, 8 warps (2M x 4N), warp tile 64x32 (4x4 m16n8k16).
// PDL: prologue (bias + weight cp.async) runs pre-wait; A/dependent reads
// post-wait; launch_dependents fires after the mainloop so the next kernel's
// prologue backfills this kernel's tail wave.

constexpr int SM_BIAS  = 0;      // 128 f32
constexpr int SM_SCALE = 512;    // 128 f32
constexpr int SM_AH    = 1024;   // [2][16384]
constexpr int SM_AL    = 33792;  // [2][16384]
constexpr int SM_BH    = 66560;  // [16384]
constexpr int SM_BL    = 82944;  // [16384]
constexpr int SMEM_TOTAL = 99328;

__device__ __forceinline__ void store_pair(__nv_bfloat16* outh, __nv_bfloat16* outl,
                                           size_t o, float a, float b) {
    __nv_bfloat162 h = __floats2bfloat162_rn(a, b);
    float2 hf = __bfloat1622float2(h);
    __nv_bfloat162 l = __floats2bfloat162_rn(a - hf.x, b - hf.y);
    *(__nv_bfloat162*)&outh[o] = h;
    *(__nv_bfloat162*)&outl[o] = l;
}

template<int MODE, bool SCALE, bool ABF16, bool OBF16, bool DUAL>
__global__ void __launch_bounds__(256, 2)
gemm_tc(const float* __restrict__ A,                 // fp32 A (when !ABF16)
        const __nv_bfloat16* __restrict__ Ah,        // bf16 A pair (when ABF16)
        const __nv_bfloat16* __restrict__ Al,
        const __nv_bfloat16* WTh,                    // [256][256]
        const __nv_bfloat16* WTl,
        const __nv_bfloat16* WTh2,                   // DUAL second set
        const __nv_bfloat16* WTl2,
        const float* __restrict__ bias,
        const float* __restrict__ residual,
        float* out,
        float* out2,
        __nv_bfloat16* __restrict__ outh,
        __nv_bfloat16* __restrict__ outl) {
    extern __shared__ __align__(1024) char sm[];
    const uint32_t smb = smem_u32(sm);
    const int tid  = threadIdx.x;
    const int wid  = tid >> 5;
    const int lane = tid & 31;
    const int row0 = blockIdx.y * 128;
    const int col0 = blockIdx.x * 128;
    const int wm = (wid & 1) * 64;
    const int wn = (wid >> 1) * 32;

    if (DUAL && blockIdx.z == 1) { WTh = WTh2; WTl = WTl2; out = out2; }

    // ---- pre-wait prologue: const data only ----
    if (tid < 128) ((float*)(sm + SM_BIAS))[tid] = bias[col0 + tid];

    const int grp = lane >> 3, lr = lane & 7;
    const uint32_t kadd = (grp >> 1) * 16;
    uint32_t saA[4], xaA[4], saB[2], xaB[2];
    #pragma unroll
    for (int mi = 0; mi < 4; mi++) {
        int r = wm + mi * 16 + (grp & 1) * 8 + lr;
        saA[mi] = (uint32_t)r * 128;
        xaA[mi] = (uint32_t)(r & 7) << 4;
    }
    #pragma unroll
    for (int nj = 0; nj < 2; nj++) {
        int r = wn + nj * 16 + (grp & 1) * 8 + lr;
        saB[nj] = (uint32_t)r * 128;
        xaB[nj] = (uint32_t)(r & 7) << 4;
    }

    auto cpB = [&](int k0) {
        uint32_t bh = smb + SM_BH;
        uint32_t bl = smb + SM_BL;
        #pragma unroll
        for (int i = 0; i < 4; i++) {
            int idx = tid + i * 256;
            int n = idx >> 3, j = idx & 7;
            uint32_t boff = SW128((uint32_t)(n * 128 + j * 16));
            size_t go = (size_t)(col0 + n) * Dn + k0 + j * 8;
            CP_ASYNC16(bh + boff, WTh + go);
            CP_ASYNC16(bl + boff, WTl + go);
        }
    };
    cpB(0);                      // weights: const (transitively wait-chained)

    GDC_WAIT;                    // ---- all dependent reads below this line ----

    if (SCALE && tid < 128) ((float*)(sm + SM_SCALE))[tid] = g_invc[row0 + tid];
    __syncthreads();

    const float* s_scale = (const float*)(sm + SM_SCALE);
    float acc[4][4][4] = {};

    auto ldsplitA = [&](int k0, int buf) {
        char* ah = sm + SM_AH + buf * 16384;
        char* al = sm + SM_AL + buf * 16384;
        float4 pa[4][2];
        #pragma unroll
        for (int i = 0; i < 4; i++) {
            int idx = tid + i * 256;
            int ar = idx >> 3;
            int c8 = (idx & 7) * 8;
            size_t off = (size_t)(row0 + ar) * Dn + k0 + c8;
            pa[i][0] = *(const float4*)&A[off];
            pa[i][1] = *(const float4*)&A[off + 4];
        }
        #pragma unroll
        for (int i = 0; i < 4; i++) {
            int idx = tid + i * 256;
            int ar = idx >> 3;
            int c8 = (idx & 7) * 8;
            float4 v0 = pa[i][0], v1 = pa[i][1];
            if (SCALE) {
                float s = s_scale[ar];
                v0.x *= s; v0.y *= s; v0.z *= s; v0.w *= s;
                v1.x *= s; v1.y *= s; v1.z *= s; v1.w *= s;
            }
            uint2 h0, l0, h1, l1;
            split_bf16x4(v0, h0, l0);
            split_bf16x4(v1, h1, l1);
            uint32_t boff = SW128((uint32_t)(ar * 128 + c8 * 2));
            *(uint4*)(ah + boff) = make_uint4(h0.x, h0.y, h1.x, h1.y);
            *(uint4*)(al + boff) = make_uint4(l0.x, l0.y, l1.x, l1.y);
        }
    };
    auto cpA = [&](int k0, int buf) {
        uint32_t ah = smb + SM_AH + buf * 16384;
        uint32_t al = smb + SM_AL + buf * 16384;
        #pragma unroll
        for (int i = 0; i < 4; i++) {
            int idx = tid + i * 256;
            int r = idx >> 3, j = idx & 7;
            uint32_t boff = SW128((uint32_t)(r * 128 + j * 16));
            size_t go = (size_t)(row0 + r) * Dn + k0 + j * 8;
            CP_ASYNC16(ah + boff, Ah + go);
            CP_ASYNC16(al + boff, Al + go);
        }
    };
    auto compute = [&](int buf) {
        uint32_t abh = smb + SM_AH + buf * 16384;
        uint32_t abl = smb + SM_AL + buf * 16384;
        uint32_t bbh = smb + SM_BH;
        uint32_t bbl = smb + SM_BL;
        #pragma unroll
        for (int ks = 0; ks < 4; ks++) {
            uint32_t kx = ks * 32 + kadd;
            uint32_t ahi[4][4], alo[4][4], bhi[4][2];
            #pragma unroll
            for (int mi = 0; mi < 4; mi++) {
                LDSM4(ahi[mi], abh + saA[mi] + (kx ^ xaA[mi]));
                LDSM4(alo[mi], abl + saA[mi] + (kx ^ xaA[mi]));
            }
            #pragma unroll
            for (int nj = 0; nj < 2; nj++) {
                uint32_t r[4];
                LDSM4(r, bbh + saB[nj] + (kx ^ xaB[nj]));
                bhi[nj * 2][0] = r[0]; bhi[nj * 2 + 1][0] = r[1];
                bhi[nj * 2][1] = r[2]; bhi[nj * 2 + 1][1] = r[3];
            }
            #pragma unroll
            for (int mi = 0; mi < 4; mi++)
                #pragma unroll
                for (int ni = 0; ni < 4; ni++)
                    MMA_BF16(acc[mi][ni], ahi[mi], bhi[ni]);
            #pragma unroll
            for (int mi = 0; mi < 4; mi++)
                #pragma unroll
                for (int ni = 0; ni < 4; ni++)
                    MMA_BF16(acc[mi][ni], alo[mi], bhi[ni]);
            uint32_t blo[4][2];
            #pragma unroll
            for (int nj = 0; nj < 2; nj++) {
                uint32_t r[4];
                LDSM4(r, bbl + saB[nj] + (kx ^ xaB[nj]));
                blo[nj * 2][0] = r[0]; blo[nj * 2 + 1][0] = r[1];
                blo[nj * 2][1] = r[2]; blo[nj * 2 + 1][1] = r[3];
            }
            #pragma unroll
            for (int mi = 0; mi < 4; mi++)
                #pragma unroll
                for (int ni = 0; ni < 4; ni++)
                    MMA_BF16(acc[mi][ni], ahi[mi], blo[ni]);
        }
    };

    constexpr int nT = 4;   // K = 256 in chunks of 64
    if (ABF16) cpA(0, 0); else ldsplitA(0, 0);
    CP_COMMIT;
    CP_WAIT0;
    __syncthreads();

    int buf = 0;
    for (int t = 0; t < nT; t++) {
        if (t + 1 < nT) {
            if (ABF16) { cpA((t + 1) * 64, buf ^ 1); CP_COMMIT; }
            else ldsplitA((t + 1) * 64, buf ^ 1);
        }
        compute(buf);
        if (t + 1 < nT) {
            __syncthreads();             // all warps done reading B(t)
            cpB((t + 1) * 64);
            CP_COMMIT;
            CP_WAIT0;                    // A(t+1) + B(t+1) arrived
            __syncthreads();
            buf ^= 1;
        }
    }

    GDC_LAUNCH;    // successor prologues may start; tail wave backfilled

    // ---- epilogue ---------------------------------------------------------
    const float* sb = (const float*)(sm + SM_BIAS);
    #pragma unroll
    for (int mi = 0; mi < 4; mi++) {
        int r0g = row0 + wm + mi * 16 + (lane >> 2);
        int r1g = r0g + 8;
        float mk0 = 1.0f, mk1 = 1.0f;
        int dr0 = 0, dr1 = 0, sr0 = 0, sr1 = 0;
        if (MODE == 1) {
            mk0 = g_maskf[r0g]; dr0 = g_dstrow[r0g];
            mk1 = g_maskf[r1g]; dr1 = g_dstrow[r1g];
        } else if (MODE == 3) {
            mk0 = g_nmaskf[r0g];
            mk1 = g_nmaskf[r1g];
        } else if (MODE == 4) {
            sr0 = g_srcrow[r0g]; dr0 = g_dstrow[r0g];
            sr1 = g_srcrow[r1g]; dr1 = g_dstrow[r1g];
        }
        #pragma unroll
        for (int ni = 0; ni < 4; ni++) {
            int cl = wn + ni * 8 + (lane & 3) * 2;
            int cg = col0 + cl;
            float b0 = sb[cl], b1 = sb[cl + 1];
            float v00 = acc[mi][ni][0] + b0, v01 = acc[mi][ni][1] + b1;
            float v10 = acc[mi][ni][2] + b0, v11 = acc[mi][ni][3] + b1;
            size_t o0 = (size_t)r0g * Dn + cg;
            size_t o1 = (size_t)r1g * Dn + cg;
            if (MODE == 0) {
                v00 = silu_f(v00); v01 = silu_f(v01);
                v10 = silu_f(v10); v11 = silu_f(v11);
            } else if (MODE == 1) {
                v00 *= mk0; v01 *= mk0; v10 *= mk1; v11 *= mk1;
                if (mk0 != 0.0f) RED_ADD_V2(&g_agg[(size_t)dr0 * Dn + cg], v00, v01);
                if (mk1 != 0.0f) RED_ADD_V2(&g_agg[(size_t)dr1 * Dn + cg], v10, v11);
            } else if (MODE == 2) {
                float2 q0 = *(const float2*)&residual[o0];
                float2 q1 = *(const float2*)&residual[o1];
                v00 += q0.x; v01 += q0.y; v10 += q1.x; v11 += q1.y;
            } else if (MODE == 3) {
                float2 q0 = *(const float2*)&residual[o0];
                float2 q1 = *(const float2*)&residual[o1];
                v00 = q0.x + v00 * mk0; v01 = q0.y + v01 * mk0;
                v10 = q1.x + v10 * mk1; v11 = q1.y + v11 * mk1;
            } else if (MODE == 4) {
                float2 p0 = *(const float2*)&g_p1[(size_t)sr0 * Dn + cg];
                float2 p1 = *(const float2*)&g_p1[(size_t)sr1 * Dn + cg];
                float2 q0 = *(const float2*)&g_p3[(size_t)dr0 * Dn + cg];
                float2 q1 = *(const float2*)&g_p3[(size_t)dr1 * Dn + cg];
                v00 = silu_f(v00 + p0.x + q0.x); v01 = silu_f(v01 + p0.y + q0.y);
                v10 = silu_f(v10 + p1.x + q1.x); v11 = silu_f(v11 + p1.y + q1.y);
            }
            if (OBF16) {
                store_pair(outh, outl, o0, v00, v01);
                store_pair(outh, outl, o1, v10, v11);
            } else {
                *(float2*)&out[o0] = make_float2(v00, v01);
                *(float2*)&out[o1] = make_float2(v10, v11);
            }
        }
    }
}

// ---------------- layernorm over last dim (256), float4 vectorized ----------
__global__ void ln_kernel(const float* __restrict__ x,
                          const float* __restrict__ gamma,
                          const float* __restrict__ beta,
                          float* __restrict__ out) {
    int v = blockIdx.x, t = threadIdx.x;   // 64 threads, 4 elems each
    float4 g = *(const float4*)&gamma[t * 4];       // const inputs pre-wait
    float4 bb = *(const float4*)&beta[t * 4];
    GDC_WAIT;
    GDC_LAUNCH;
    float4 val = *(const float4*)&x[(size_t)v * Dn + t * 4];
    float s  = val.x + val.y + val.z + val.w;
    float s2 = val.x * val.x + val.y * val.y + val.z * val.z + val.w * val.w;
    #pragma unroll
    for (int o = 16; o > 0; o >>= 1) {
        s  += __shfl_xor_sync(0xffffffffu, s,  o);
        s2 += __shfl_xor_sync(0xffffffffu, s2, o);
    }
    __shared__ float ws[2], ws2[2];
    int w = t >> 5;
    if ((t & 31) == 0) { ws[w] = s; ws2[w] = s2; }
    __syncthreads();
    float sa  = ws[0] + ws[1];
    float sa2 = ws2[0] + ws2[1];
    float mean = sa * (1.0f / 256.0f);
    float var  = sa2 * (1.0f / 256.0f) - mean * mean;
    float inv  = rsqrtf(var + 1e-5f);
    float4 o;
    o.x = (val.x - mean) * inv * g.x + bb.x;
    o.y = (val.y - mean) * inv * g.y + bb.y;
    o.z = (val.z - mean) * inv * g.z + bb.z;
    o.w = (val.w - mean) * inv * g.w + bb.w;
    *(float4*)&out[(size_t)v * Dn + t * 4] = o;
}

// ---------------- PDL launch helper ------------------------------------------
template<typename F, typename... Args>
static void launchP(F f, dim3 g, dim3 b, size_t smem, Args... args) {
    cudaLaunchConfig_t cfg = {};
    cfg.gridDim = g;
    cfg.blockDim = b;
    cfg.dynamicSmemBytes = smem;
    cfg.stream = 0;
    cudaLaunchAttribute at;
    at.id = cudaLaunchAttributeProgrammaticStreamSerialization;
    at.val.programmaticStreamSerializationAllowed = 1;
    cfg.attrs = &at;
    cfg.numAttrs = 1;
    cudaLaunchKernelEx(&cfg, f, args...);
}

// ---------------- launch ------------------------------------------------------
extern "C" void kernel_launch(void* const* d_in, const int* in_sizes, int n_in,
                              void* d_out, int out_size) {
    const float* node_feat = (const float*)d_in[0];
    const float* edge_feat = (const float*)d_in[1];
    const int*   edge_index = (const int*)d_in[2];
    const void*  node_mask = d_in[3];
    const void*  edge_mask = d_in[4];
    const float* tw1 = (const float*)d_in[5];
    const float* tb1 = (const float*)d_in[6];
    const float* tw2 = (const float*)d_in[7];
    const float* tb2 = (const float*)d_in[8];
    const float* nw1 = (const float*)d_in[9];
    const float* nb1 = (const float*)d_in[10];
    const float* nw2 = (const float*)d_in[11];
    const float* nb2 = (const float*)d_in[12];
    const float* ew1 = (const float*)d_in[13];
    const float* eb1 = (const float*)d_in[14];
    const float* ew2 = (const float*)d_in[15];
    const float* eb2 = (const float*)d_in[16];
    const float* gamma = (const float*)d_in[17];
    const float* beta  = (const float*)d_in[18];

    float* out = (float*)d_out;

    float *hidden, *msg, *agg, *hn, *node, *cnt, *p1, *p3, *nfs, *zb;
    __nv_bfloat16 *wth, *wtl;
    cudaGetSymbolAddress((void**)&hidden, g_buf1);
    cudaGetSymbolAddress((void**)&msg,    g_msg);
    cudaGetSymbolAddress((void**)&agg,    g_agg);
    cudaGetSymbolAddress((void**)&hn,     g_hn);
    cudaGetSymbolAddress((void**)&node,   g_node);
    cudaGetSymbolAddress((void**)&cnt,    g_cnt);
    cudaGetSymbolAddress((void**)&p1,     g_p1);
    cudaGetSymbolAddress((void**)&p3,     g_p3);
    cudaGetSymbolAddress((void**)&nfs,    g_nfs);
    cudaGetSymbolAddress((void**)&zb,     g_zero256);
    cudaGetSymbolAddress((void**)&wth,    g_wth);
    cudaGetSymbolAddress((void**)&wtl,    g_wtl);

    __nv_bfloat16* hidh = (__nv_bfloat16*)hidden;
    __nv_bfloat16* hidl = hidh + (size_t)ME * Dn;
    __nv_bfloat16* msgh = (__nv_bfloat16*)msg;
    __nv_bfloat16* msgl = msgh + (size_t)ME * Dn;
    __nv_bfloat16* hnh  = (__nv_bfloat16*)hn;
    __nv_bfloat16* hnl  = hnh + (size_t)MN * Dn;
    __nv_bfloat16* nfh  = (__nv_bfloat16*)nfs;
    __nv_bfloat16* nfl  = nfh + (size_t)MN * Dn;

    cudaFuncSetAttribute(gemm_tc<5, false, true , false, true >, cudaFuncAttributeMaxDynamicSharedMemorySize, SMEM_TOTAL);
    cudaFuncSetAttribute(gemm_tc<4, false, false, true , false>, cudaFuncAttributeMaxDynamicSharedMemorySize, SMEM_TOTAL);
    cudaFuncSetAttribute(gemm_tc<1, false, true , true , false>, cudaFuncAttributeMaxDynamicSharedMemorySize, SMEM_TOTAL);
    cudaFuncSetAttribute(gemm_tc<0, false, true , true , false>, cudaFuncAttributeMaxDynamicSharedMemorySize, SMEM_TOTAL);
    cudaFuncSetAttribute(gemm_tc<2, false, true , false, false>, cudaFuncAttributeMaxDynamicSharedMemorySize, SMEM_TOTAL);
    cudaFuncSetAttribute(gemm_tc<0, true , false, true , false>, cudaFuncAttributeMaxDynamicSharedMemorySize, SMEM_TOTAL);
    cudaFuncSetAttribute(gemm_tc<3, false, true , false, false>, cudaFuncAttributeMaxDynamicSharedMemorySize, SMEM_TOTAL);

    // zero scratch (plain memset nodes)
    cudaMemsetAsync(agg, 0, (size_t)MN * Dn * sizeof(float));
    cudaMemsetAsync(cnt, 0, (size_t)MN * sizeof(float));

    // weight transpose + bf16 split (plain launch, head of PDL chain)
    WSrcs ws;
    ws.p[0] = tw1;          ws.p[1] = tw1 + 65536;  ws.p[2] = tw1 + 131072;
    ws.p[3] = tw2;          ws.p[4] = ew1;          ws.p[5] = ew2;
    ws.p[6] = nw1;          ws.p[7] = nw2;
    prep_weights_all<<<dim3(8, 8, 8), dim3(32, 8)>>>(ws, wth, wtl);

    launchP(split_pair, dim3((MN * Dn / 4) / 256), dim3(256), 0,
            (const float4*)node_feat, (uint2*)nfh, (uint2*)nfl);
    launchP(prep_edges, dim3(ME / 256), dim3(256), 0, edge_index, edge_mask);

    dim3 ge(2, ME / 128);
    dim3 gn(2, MN / 128);
    dim3 gn2(2, MN / 128, 2);
    // P1 = nf @ W1a (z=0), P3 = nf @ W1c (z=1) — pure cp.async A
    launchP(gemm_tc<5, false, true , false, true >, gn2, dim3(256), (size_t)SMEM_TOTAL,
            (const float*)nullptr, (const __nv_bfloat16*)nfh, (const __nv_bfloat16*)nfl,
            (const __nv_bfloat16*)(wth + OW_T1A), (const __nv_bfloat16*)(wtl + OW_T1A),
            (const __nv_bfloat16*)(wth + OW_T1C), (const __nv_bfloat16*)(wtl + OW_T1C),
            (const float*)zb, (const float*)nullptr, p1, p3,
            (__nv_bfloat16*)nullptr, (__nv_bfloat16*)nullptr);
    // triplet layer1: silu(ef@W1b + P1[src] + P3[dst] + tb1) -> hidden pair
    launchP(gemm_tc<4, false, false, true , false>, ge, dim3(256), (size_t)SMEM_TOTAL,
            edge_feat, (const __nv_bfloat16*)nullptr, (const __nv_bfloat16*)nullptr,
            (const __nv_bfloat16*)(wth + OW_T1B), (const __nv_bfloat16*)(wtl + OW_T1B),
            (const __nv_bfloat16*)nullptr, (const __nv_bfloat16*)nullptr,
            tb1, (const float*)nullptr, (float*)nullptr, (float*)nullptr, hidh, hidl);
    // msg = (hidden@tw2+tb2)*mask -> pair + red.v2 to agg
    launchP(gemm_tc<1, false, true , true , false>, ge, dim3(256), (size_t)SMEM_TOTAL,
            (const float*)nullptr, (const __nv_bfloat16*)hidh, (const __nv_bfloat16*)hidl,
            (const __nv_bfloat16*)(wth + OW_TW2), (const __nv_bfloat16*)(wtl + OW_TW2),
            (const __nv_bfloat16*)nullptr, (const __nv_bfloat16*)nullptr,
            tb2, (const float*)nullptr, (float*)nullptr, (float*)nullptr, msgh, msgl);
    // invc + node mask (needs cnt complete — chained via PDL waits)
    launchP(prep_nodes, dim3(MN / 256), dim3(256), 0, node_mask, edge_mask);
    // edge update layer1 (silu) -> hidden pair
    launchP(gemm_tc<0, false, true , true , false>, ge, dim3(256), (size_t)SMEM_TOTAL,
            (const float*)nullptr, (const __nv_bfloat16*)msgh, (const __nv_bfloat16*)msgl,
            (const __nv_bfloat16*)(wth + OW_EW1), (const __nv_bfloat16*)(wtl + OW_EW1),
            (const __nv_bfloat16*)nullptr, (const __nv_bfloat16*)nullptr,
            eb1, (const float*)nullptr, (float*)nullptr, (float*)nullptr, hidh, hidl);
    // edge_out = edge_feat + layer2 (fp32)
    launchP(gemm_tc<2, false, true , false, false>, ge, dim3(256), (size_t)SMEM_TOTAL,
            (const float*)nullptr, (const __nv_bfloat16*)hidh, (const __nv_bfloat16*)hidl,
            (const __nv_bfloat16*)(wth + OW_EW2), (const __nv_bfloat16*)(wtl + OW_EW2),
            (const __nv_bfloat16*)nullptr, (const __nv_bfloat16*)nullptr,
            eb2, edge_feat, out + (size_t)MN * Dn, (float*)nullptr,
            (__nv_bfloat16*)nullptr, (__nv_bfloat16*)nullptr);
    // node layer1 on agg*invc (silu) -> hn pair
    launchP(gemm_tc<0, true , false, true , false>, gn, dim3(256), (size_t)SMEM_TOTAL,
            (const float*)agg, (const __nv_bfloat16*)nullptr, (const __nv_bfloat16*)nullptr,
            (const __nv_bfloat16*)(wth + OW_NW1), (const __nv_bfloat16*)(wtl + OW_NW1),
            (const __nv_bfloat16*)nullptr, (const __nv_bfloat16*)nullptr,
            nb1, (const float*)nullptr, (float*)nullptr, (float*)nullptr, hnh, hnl);
    // node = node_feat + layer2 * node_mask (fp32)
    launchP(gemm_tc<3, false, true , false, false>, gn, dim3(256), (size_t)SMEM_TOTAL,
            (const float*)nullptr, (const __nv_bfloat16*)hnh, (const __nv_bfloat16*)hnl,
            (const __nv_bfloat16*)(wth + OW_NW2), (const __nv_bfloat16*)(wtl + OW_NW2),
            (const __nv_bfloat16*)nullptr, (const __nv_bfloat16*)nullptr,
            nb2, node_feat, node, (float*)nullptr,
            (__nv_bfloat16*)nullptr, (__nv_bfloat16*)nullptr);
    // layernorm (float4, 64 threads/row)
    launchP(ln_kernel, dim3(MN), dim3(64), 0, (const float*)node, gamma, beta, out);
}

// round 16
// speedup vs baseline: 1.0087x; 1.0087x over previous
#include <cuda_runtime.h>
#include <cuda_bf16.h>
#include <cstdint>
#include <math.h>

// Problem constants
#define Bn 16
#define Nn 1024
#define En 16384
#define Dn 256
constexpr int ME = Bn * En;   // 262144 edge rows
constexpr int MN = Bn * Nn;   // 16384 node rows

// ============================ PTX helpers ===================================
__device__ __forceinline__ uint32_t smem_u32(const void* p) {
    uint32_t a;
    asm("{ .reg .u64 t; cvta.to.shared.u64 t, %1; cvt.u32.u64 %0, t; }"
        : "=r"(a) : "l"(p));
    return a;
}

#define LDSM4(r, addr) \
    asm volatile("ldmatrix.sync.aligned.m8n8.x4.shared.b16 {%0,%1,%2,%3}, [%4];" \
        : "=r"((r)[0]), "=r"((r)[1]), "=r"((r)[2]), "=r"((r)[3]) : "r"(addr))

#define MMA_BF16(d, a, b) \
    asm volatile("mma.sync.aligned.m16n8k16.row.col.f32.bf16.bf16.f32 " \
        "{%0,%1,%2,%3}, {%4,%5,%6,%7}, {%8,%9}, {%0,%1,%2,%3};" \
        : "+f"((d)[0]), "+f"((d)[1]), "+f"((d)[2]), "+f"((d)[3]) \
        : "r"((a)[0]), "r"((a)[1]), "r"((a)[2]), "r"((a)[3]), \
          "r"((b)[0]), "r"((b)[1]))

#define CP_ASYNC16(dst, src) \
    asm volatile("cp.async.cg.shared.global [%0], [%1], 16;" :: "r"(dst), "l"(src))
#define CP_COMMIT asm volatile("cp.async.commit_group;" ::: "memory")
#define CP_WAIT0  asm volatile("cp.async.wait_group 0;" ::: "memory")

#define RED_ADD_V2(p, a, b) \
    asm volatile("red.global.add.v2.f32 [%0], {%1,%2};" :: "l"(p), "f"(a), "f"(b) : "memory")

// Programmatic Dependent Launch (sm_90 PTX, valid on compute_103)
#define GDC_WAIT   asm volatile("griddepcontrol.wait;" ::: "memory")
#define GDC_LAUNCH asm volatile("griddepcontrol.launch_dependents;" ::: "memory")

#define SW128(x) ((x) ^ (((x) >> 3) & 0x70))

// ============================ scratch globals ================================
__device__ float g_buf1[(size_t)ME * Dn];   // hidden (bf16 hi/lo pair alias)
__device__ float g_msg [(size_t)ME * Dn];   // msg    (bf16 hi/lo pair alias)
__device__ float g_agg [(size_t)MN * Dn];   // fp32 (atomics)
__device__ float g_hn  [(size_t)MN * Dn];   // hn     (bf16 hi/lo pair alias)
__device__ float g_node[(size_t)MN * Dn];   // fp32 pre-LN
__device__ float g_p1  [(size_t)MN * Dn];   // node_feat @ W1a (fp32)
__device__ float g_p3  [(size_t)MN * Dn];   // node_feat @ W1c (fp32)
__device__ float g_nfs [(size_t)MN * Dn];   // node_feat pre-split (bf16 pair)
__device__ float g_cnt [MN];
__device__ float g_invc[MN];
__device__ int   g_srcrow[ME];
__device__ int   g_dstrow[ME];
__device__ float g_maskf [ME];
__device__ float g_nmaskf[MN];
__device__ float g_zero256[256];
// pre-transposed + bf16-split weights, 8 matrices of [256][256]
__device__ __nv_bfloat16 g_wth[524288];
__device__ __nv_bfloat16 g_wtl[524288];
constexpr size_t OW_T1A = 0,      OW_T1B = 65536,  OW_T1C = 131072,
                 OW_TW2 = 196608, OW_EW1 = 262144, OW_EW2 = 327680,
                 OW_NW1 = 393216, OW_NW2 = 458752;

__device__ __forceinline__ float silu_f(float x) { return x / (1.0f + __expf(-x)); }

// mask dtype: 0=float32, 1=uint8, 2=int32 (sniff first 16 words of buffer)
__device__ __forceinline__ int sniff_dt(const unsigned int* m) {
    bool big = false, up = false;
    #pragma unroll
    for (int i = 0; i < 16; i++) {
        unsigned int w = m[i];
        unsigned char b0 = w & 0xff, b1 = (w >> 8) & 0xff,
                      b2 = (w >> 16) & 0xff, b3 = (w >> 24) & 0xff;
        if (b0 >= 2 || b1 >= 2 || b2 >= 2 || b3 >= 2) big = true;
        if (b1 | b2 | b3) up = true;
    }
    return big ? 0 : (up ? 1 : 2);
}

__device__ __forceinline__ float read_mask(const void* p, int i, int dt) {
    if (dt == 0) return ((const float*)p)[i];
    if (dt == 1) return ((const unsigned char*)p)[i] ? 1.0f : 0.0f;
    return ((const int*)p)[i] ? 1.0f : 0.0f;
}

__device__ __forceinline__ void split_bf16x4(float4 v, uint2& hi, uint2& lo) {
    __nv_bfloat162 h01 = __floats2bfloat162_rn(v.x, v.y);
    __nv_bfloat162 h23 = __floats2bfloat162_rn(v.z, v.w);
    float2 f01 = __bfloat1622float2(h01);
    float2 f23 = __bfloat1622float2(h23);
    __nv_bfloat162 l01 = __floats2bfloat162_rn(v.x - f01.x, v.y - f01.y);
    __nv_bfloat162 l23 = __floats2bfloat162_rn(v.z - f23.x, v.w - f23.y);
    hi.x = *(uint32_t*)&h01; hi.y = *(uint32_t*)&h23;
    lo.x = *(uint32_t*)&l01; lo.y = *(uint32_t*)&l23;
}

// ---------------- small prep kernels (launch_dependents AFTER writes) --------
__global__ void prep_edges(const int* __restrict__ edge_index,
                           const void* __restrict__ edge_mask) {
    __shared__ int sdt;
    GDC_WAIT;
    if (threadIdx.x == 0) sdt = sniff_dt((const unsigned int*)edge_mask);
    __syncthreads();
    int dt = sdt;
    int r = blockIdx.x * blockDim.x + threadIdx.x;
    if (r < ME) {
        int b = r >> 14;
        int e = r & (En - 1);
        int src = edge_index[(size_t)b * 2 * En + e];
        int dst = edge_index[(size_t)b * 2 * En + En + e];
        float m = (read_mask(edge_mask, r, dt) != 0.0f) ? 1.0f : 0.0f;
        g_srcrow[r] = b * Nn + src;
        g_dstrow[r] = b * Nn + dst;
        g_maskf[r]  = m;
        if (m != 0.0f) atomicAdd(&g_cnt[b * Nn + dst], 1.0f);
    }
    GDC_LAUNCH;
}

__global__ void prep_nodes(const void* __restrict__ node_mask,
                           const void* __restrict__ edge_mask) {
    __shared__ int sdt;
    GDC_WAIT;
    if (threadIdx.x == 0) sdt = sniff_dt((const unsigned int*)edge_mask);
    __syncthreads();
    int dt = sdt;
    int v = blockIdx.x * blockDim.x + threadIdx.x;
    if (v < MN) {
        g_invc[v]   = 1.0f / fmaxf(g_cnt[v], 1.0f);
        g_nmaskf[v] = (read_mask(node_mask, v, dt) != 0.0f) ? 1.0f : 0.0f;
    }
    GDC_LAUNCH;
}

// elementwise fp32 -> bf16 hi/lo pair split (node_feat)
__global__ void split_pair(const float4* __restrict__ src,
                           uint2* __restrict__ dsth, uint2* __restrict__ dstl) {
    GDC_WAIT;
    int i = blockIdx.x * blockDim.x + threadIdx.x;
    uint2 hi, lo;
    split_bf16x4(src[i], hi, lo);
    dsth[i] = hi;
    dstl[i] = lo;
    GDC_LAUNCH;
}

// All 8 weight transposes in one launch; smem-tile coalesced.
struct WSrcs { const float* p[8]; };
__global__ void prep_weights_all(WSrcs srcs,
                                 __nv_bfloat16* __restrict__ wth,
                                 __nv_bfloat16* __restrict__ wtl) {
    __shared__ float tile[32][33];
    const float* src = srcs.p[blockIdx.z];
    int kt = blockIdx.x * 32, nt = blockIdx.y * 32;
    #pragma unroll
    for (int i = threadIdx.y; i < 32; i += 8)
        tile[i][threadIdx.x] = src[(size_t)(kt + i) * 256 + nt + threadIdx.x];
    __syncthreads();
    size_t base = (size_t)blockIdx.z * 65536;
    #pragma unroll
    for (int i = threadIdx.y; i < 32; i += 8) {
        int n = nt + i, k = kt + threadIdx.x;
        float v = tile[threadIdx.x][i];
        __nv_bfloat16 h = __float2bfloat16_rn(v);
        wth[base + (size_t)n * 256 + k] = h;
        wtl[base + (size_t)n * 256 + k] = __float2bfloat16_rn(v - __bfloat162float(h));
    }
    GDC_LAUNCH;
}

// ============================ tensor-core GEMM (mma.sync) ====================
// out[M,256] = A[M,256] @ W[256,256] via bf16x3 (AhiBhi + AloBhi + AhiBlo).
// Block tile 128x128, 8 warps (2M x 4N), warp tile 64x32 (4x4 m16n8k16).
// WPOS: where griddepcontrol.wait sits.
//   0 = before dependent A/scale reads (mainloop depends on predecessor)
//   1 = after mainloop (A readable transitively; only epilogue is dependent)
//   2 = no wait (all inputs ready transitively at launch)
// launch_dependents fires post-mainloop so successors backfill the tail wave.

constexpr int SM_BIAS  = 0;      // 128 f32
constexpr int SM_SCALE = 512;    // 128 f32
constexpr int SM_AH    = 1024;   // [2][16384]
constexpr int SM_AL    = 33792;  // [2][16384]
constexpr int SM_BH    = 66560;  // [16384]
constexpr int SM_BL    = 82944;  // [16384]
constexpr int SMEM_TOTAL = 99328;

__device__ __forceinline__ void store_pair(__nv_bfloat16* outh, __nv_bfloat16* outl,
                                           size_t o, float a, float b) {
    __nv_bfloat162 h = __floats2bfloat162_rn(a, b);
    float2 hf = __bfloat1622float2(h);
    __nv_bfloat162 l = __floats2bfloat162_rn(a - hf.x, b - hf.y);
    *(__nv_bfloat162*)&outh[o] = h;
    *(__nv_bfloat162*)&outl[o] = l;
}

template<int MODE, bool SCALE, bool ABF16, bool OBF16, bool DUAL, int WPOS>
__global__ void __launch_bounds__(256, 2)
gemm_tc(const float* __restrict__ A,                 // fp32 A (when !ABF16)
        const __nv_bfloat16* __restrict__ Ah,        // bf16 A pair (when ABF16)
        const __nv_bfloat16* __restrict__ Al,
        const __nv_bfloat16* WTh,                    // [256][256]
        const __nv_bfloat16* WTl,
        const __nv_bfloat16* WTh2,                   // DUAL second set
        const __nv_bfloat16* WTl2,
        const float* __restrict__ bias,
        const float* __restrict__ residual,
        float* out,
        float* out2,
        __nv_bfloat16* __restrict__ outh,
        __nv_bfloat16* __restrict__ outl) {
    extern __shared__ __align__(1024) char sm[];
    const uint32_t smb = smem_u32(sm);
    const int tid  = threadIdx.x;
    const int wid  = tid >> 5;
    const int lane = tid & 31;
    const int row0 = blockIdx.y * 128;
    const int col0 = blockIdx.x * 128;
    const int wm = (wid & 1) * 64;
    const int wn = (wid >> 1) * 32;

    if (DUAL && blockIdx.z == 1) { WTh = WTh2; WTl = WTl2; out = out2; }

    // ---- pre-wait prologue: const / transitively-ready data ----
    if (tid < 128) ((float*)(sm + SM_BIAS))[tid] = bias[col0 + tid];

    const int grp = lane >> 3, lr = lane & 7;
    const uint32_t kadd = (grp >> 1) * 16;
    uint32_t saA[4], xaA[4], saB[2], xaB[2];
    #pragma unroll
    for (int mi = 0; mi < 4; mi++) {
        int r = wm + mi * 16 + (grp & 1) * 8 + lr;
        saA[mi] = (uint32_t)r * 128;
        xaA[mi] = (uint32_t)(r & 7) << 4;
    }
    #pragma unroll
    for (int nj = 0; nj < 2; nj++) {
        int r = wn + nj * 16 + (grp & 1) * 8 + lr;
        saB[nj] = (uint32_t)r * 128;
        xaB[nj] = (uint32_t)(r & 7) << 4;
    }

    auto cpB = [&](int k0) {
        uint32_t bh = smb + SM_BH;
        uint32_t bl = smb + SM_BL;
        #pragma unroll
        for (int i = 0; i < 4; i++) {
            int idx = tid + i * 256;
            int n = idx >> 3, j = idx & 7;
            uint32_t boff = SW128((uint32_t)(n * 128 + j * 16));
            size_t go = (size_t)(col0 + n) * Dn + k0 + j * 8;
            CP_ASYNC16(bh + boff, WTh + go);
            CP_ASYNC16(bl + boff, WTl + go);
        }
    };
    cpB(0);

    if (WPOS == 0) {
        GDC_WAIT;                // mainloop inputs depend on predecessor
        if (SCALE && tid < 128) ((float*)(sm + SM_SCALE))[tid] = g_invc[row0 + tid];
    }
    __syncthreads();

    const float* s_scale = (const float*)(sm + SM_SCALE);
    float acc[4][4][4] = {};

    auto ldsplitA = [&](int k0, int buf) {
        char* ah = sm + SM_AH + buf * 16384;
        char* al = sm + SM_AL + buf * 16384;
        float4 pa[4][2];
        #pragma unroll
        for (int i = 0; i < 4; i++) {
            int idx = tid + i * 256;
            int ar = idx >> 3;
            int c8 = (idx & 7) * 8;
            size_t off = (size_t)(row0 + ar) * Dn + k0 + c8;
            pa[i][0] = *(const float4*)&A[off];
            pa[i][1] = *(const float4*)&A[off + 4];
        }
        #pragma unroll
        for (int i = 0; i < 4; i++) {
            int idx = tid + i * 256;
            int ar = idx >> 3;
            int c8 = (idx & 7) * 8;
            float4 v0 = pa[i][0], v1 = pa[i][1];
            if (SCALE) {
                float s = s_scale[ar];
                v0.x *= s; v0.y *= s; v0.z *= s; v0.w *= s;
                v1.x *= s; v1.y *= s; v1.z *= s; v1.w *= s;
            }
            uint2 h0, l0, h1, l1;
            split_bf16x4(v0, h0, l0);
            split_bf16x4(v1, h1, l1);
            uint32_t boff = SW128((uint32_t)(ar * 128 + c8 * 2));
            *(uint4*)(ah + boff) = make_uint4(h0.x, h0.y, h1.x, h1.y);
            *(uint4*)(al + boff) = make_uint4(l0.x, l0.y, l1.x, l1.y);
        }
    };
    auto cpA = [&](int k0, int buf) {
        uint32_t ah = smb + SM_AH + buf * 16384;
        uint32_t al = smb + SM_AL + buf * 16384;
        #pragma unroll
        for (int i = 0; i < 4; i++) {
            int idx = tid + i * 256;
            int r = idx >> 3, j = idx & 7;
            uint32_t boff = SW128((uint32_t)(r * 128 + j * 16));
            size_t go = (size_t)(row0 + r) * Dn + k0 + j * 8;
            CP_ASYNC16(ah + boff, Ah + go);
            CP_ASYNC16(al + boff, Al + go);
        }
    };
    auto compute = [&](int buf) {
        uint32_t abh = smb + SM_AH + buf * 16384;
        uint32_t abl = smb + SM_AL + buf * 16384;
        uint32_t bbh = smb + SM_BH;
        uint32_t bbl = smb + SM_BL;
        #pragma unroll
        for (int ks = 0; ks < 4; ks++) {
            uint32_t kx = ks * 32 + kadd;
            uint32_t ahi[4][4], alo[4][4], bhi[4][2];
            #pragma unroll
            for (int mi = 0; mi < 4; mi++) {
                LDSM4(ahi[mi], abh + saA[mi] + (kx ^ xaA[mi]));
                LDSM4(alo[mi], abl + saA[mi] + (kx ^ xaA[mi]));
            }
            #pragma unroll
            for (int nj = 0; nj < 2; nj++) {
                uint32_t r[4];
                LDSM4(r, bbh + saB[nj] + (kx ^ xaB[nj]));
                bhi[nj * 2][0] = r[0]; bhi[nj * 2 + 1][0] = r[1];
                bhi[nj * 2][1] = r[2]; bhi[nj * 2 + 1][1] = r[3];
            }
            #pragma unroll
            for (int mi = 0; mi < 4; mi++)
                #pragma unroll
                for (int ni = 0; ni < 4; ni++)
                    MMA_BF16(acc[mi][ni], ahi[mi], bhi[ni]);
            #pragma unroll
            for (int mi = 0; mi < 4; mi++)
                #pragma unroll
                for (int ni = 0; ni < 4; ni++)
                    MMA_BF16(acc[mi][ni], alo[mi], bhi[ni]);
            uint32_t blo[4][2];
            #pragma unroll
            for (int nj = 0; nj < 2; nj++) {
                uint32_t r[4];
                LDSM4(r, bbl + saB[nj] + (kx ^ xaB[nj]));
                blo[nj * 2][0] = r[0]; blo[nj * 2 + 1][0] = r[1];
                blo[nj * 2][1] = r[2]; blo[nj * 2 + 1][1] = r[3];
            }
            #pragma unroll
            for (int mi = 0; mi < 4; mi++)
                #pragma unroll
                for (int ni = 0; ni < 4; ni++)
                    MMA_BF16(acc[mi][ni], ahi[mi], blo[ni]);
        }
    };

    constexpr int nT = 4;   // K = 256 in chunks of 64
    if (ABF16) cpA(0, 0); else ldsplitA(0, 0);
    CP_COMMIT;
    CP_WAIT0;
    __syncthreads();

    int buf = 0;
    for (int t = 0; t < nT; t++) {
        if (t + 1 < nT) {
            if (ABF16) { cpA((t + 1) * 64, buf ^ 1); CP_COMMIT; }
            else ldsplitA((t + 1) * 64, buf ^ 1);
        }
        compute(buf);
        if (t + 1 < nT) {
            __syncthreads();             // all warps done reading B(t)
            cpB((t + 1) * 64);
            CP_COMMIT;
            CP_WAIT0;                    // A(t+1) + B(t+1) arrived
            __syncthreads();
            buf ^= 1;
        }
    }

    if (WPOS == 1) GDC_WAIT;   // epilogue inputs depend on predecessor
    GDC_LAUNCH;                // successors may start; tail wave backfilled

    // ---- epilogue ---------------------------------------------------------
    const float* sb = (const float*)(sm + SM_BIAS);
    #pragma unroll
    for (int mi = 0; mi < 4; mi++) {
        int r0g = row0 + wm + mi * 16 + (lane >> 2);
        int r1g = r0g + 8;
        float mk0 = 1.0f, mk1 = 1.0f;
        int dr0 = 0, dr1 = 0, sr0 = 0, sr1 = 0;
        if (MODE == 1) {
            mk0 = g_maskf[r0g]; dr0 = g_dstrow[r0g];
            mk1 = g_maskf[r1g]; dr1 = g_dstrow[r1g];
        } else if (MODE == 3) {
            mk0 = g_nmaskf[r0g];
            mk1 = g_nmaskf[r1g];
        } else if (MODE == 4) {
            sr0 = g_srcrow[r0g]; dr0 = g_dstrow[r0g];
            sr1 = g_srcrow[r1g]; dr1 = g_dstrow[r1g];
        }
        #pragma unroll
        for (int ni = 0; ni < 4; ni++) {
            int cl = wn + ni * 8 + (lane & 3) * 2;
            int cg = col0 + cl;
            float b0 = sb[cl], b1 = sb[cl + 1];
            float v00 = acc[mi][ni][0] + b0, v01 = acc[mi][ni][1] + b1;
            float v10 = acc[mi][ni][2] + b0, v11 = acc[mi][ni][3] + b1;
            size_t o0 = (size_t)r0g * Dn + cg;
            size_t o1 = (size_t)r1g * Dn + cg;
            if (MODE == 0) {
                v00 = silu_f(v00); v01 = silu_f(v01);
                v10 = silu_f(v10); v11 = silu_f(v11);
            } else if (MODE == 1) {
                v00 *= mk0; v01 *= mk0; v10 *= mk1; v11 *= mk1;
                if (mk0 != 0.0f) RED_ADD_V2(&g_agg[(size_t)dr0 * Dn + cg], v00, v01);
                if (mk1 != 0.0f) RED_ADD_V2(&g_agg[(size_t)dr1 * Dn + cg], v10, v11);
            } else if (MODE == 2) {
                float2 q0 = *(const float2*)&residual[o0];
                float2 q1 = *(const float2*)&residual[o1];
                v00 += q0.x; v01 += q0.y; v10 += q1.x; v11 += q1.y;
            } else if (MODE == 3) {
                float2 q0 = *(const float2*)&residual[o0];
                float2 q1 = *(const float2*)&residual[o1];
                v00 = q0.x + v00 * mk0; v01 = q0.y + v01 * mk0;
                v10 = q1.x + v10 * mk1; v11 = q1.y + v11 * mk1;
            } else if (MODE == 4) {
                float2 p0 = *(const float2*)&g_p1[(size_t)sr0 * Dn + cg];
                float2 p1 = *(const float2*)&g_p1[(size_t)sr1 * Dn + cg];
                float2 q0 = *(const float2*)&g_p3[(size_t)dr0 * Dn + cg];
                float2 q1 = *(const float2*)&g_p3[(size_t)dr1 * Dn + cg];
                v00 = silu_f(v00 + p0.x + q0.x); v01 = silu_f(v01 + p0.y + q0.y);
                v10 = silu_f(v10 + p1.x + q1.x); v11 = silu_f(v11 + p1.y + q1.y);
            }
            if (OBF16) {
                store_pair(outh, outl, o0, v00, v01);
                store_pair(outh, outl, o1, v10, v11);
            } else {
                *(float2*)&out[o0] = make_float2(v00, v01);
                *(float2*)&out[o1] = make_float2(v10, v11);
            }
        }
    }
}

// ---------------- layernorm over last dim (256), float4 vectorized ----------
__global__ void ln_kernel(const float* __restrict__ x,
                          const float* __restrict__ gamma,
                          const float* __restrict__ beta,
                          float* __restrict__ out) {
    int v = blockIdx.x, t = threadIdx.x;   // 64 threads, 4 elems each
    float4 g = *(const float4*)&gamma[t * 4];       // const inputs pre-wait
    float4 bb = *(const float4*)&beta[t * 4];
    GDC_WAIT;
    GDC_LAUNCH;
    float4 val = *(const float4*)&x[(size_t)v * Dn + t * 4];
    float s  = val.x + val.y + val.z + val.w;
    float s2 = val.x * val.x + val.y * val.y + val.z * val.z + val.w * val.w;
    #pragma unroll
    for (int o = 16; o > 0; o >>= 1) {
        s  += __shfl_xor_sync(0xffffffffu, s,  o);
        s2 += __shfl_xor_sync(0xffffffffu, s2, o);
    }
    __shared__ float ws[2], ws2[2];
    int w = t >> 5;
    if ((t & 31) == 0) { ws[w] = s; ws2[w] = s2; }
    __syncthreads();
    float sa  = ws[0] + ws[1];
    float sa2 = ws2[0] + ws2[1];
    float mean = sa * (1.0f / 256.0f);
    float var  = sa2 * (1.0f / 256.0f) - mean * mean;
    float inv  = rsqrtf(var + 1e-5f);
    float4 o;
    o.x = (val.x - mean) * inv * g.x + bb.x;
    o.y = (val.y - mean) * inv * g.y + bb.y;
    o.z = (val.z - mean) * inv * g.z + bb.z;
    o.w = (val.w - mean) * inv * g.w + bb.w;
    *(float4*)&out[(size_t)v * Dn + t * 4] = o;
}

// ---------------- PDL launch helper ------------------------------------------
template<typename F, typename... Args>
static void launchP(F f, dim3 g, dim3 b, size_t smem, Args... args) {
    cudaLaunchConfig_t cfg = {};
    cfg.gridDim = g;
    cfg.blockDim = b;
    cfg.dynamicSmemBytes = smem;
    cfg.stream = 0;
    cudaLaunchAttribute at;
    at.id = cudaLaunchAttributeProgrammaticStreamSerialization;
    at.val.programmaticStreamSerializationAllowed = 1;
    cfg.attrs = &at;
    cfg.numAttrs = 1;
    cudaLaunchKernelEx(&cfg, f, args...);
}

// ---------------- launch ------------------------------------------------------
extern "C" void kernel_launch(void* const* d_in, const int* in_sizes, int n_in,
                              void* d_out, int out_size) {
    const float* node_feat = (const float*)d_in[0];
    const float* edge_feat = (const float*)d_in[1];
    const int*   edge_index = (const int*)d_in[2];
    const void*  node_mask = d_in[3];
    const void*  edge_mask = d_in[4];
    const float* tw1 = (const float*)d_in[5];
    const float* tb1 = (const float*)d_in[6];
    const float* tw2 = (const float*)d_in[7];
    const float* tb2 = (const float*)d_in[8];
    const float* nw1 = (const float*)d_in[9];
    const float* nb1 = (const float*)d_in[10];
    const float* nw2 = (const float*)d_in[11];
    const float* nb2 = (const float*)d_in[12];
    const float* ew1 = (const float*)d_in[13];
    const float* eb1 = (const float*)d_in[14];
    const float* ew2 = (const float*)d_in[15];
    const float* eb2 = (const float*)d_in[16];
    const float* gamma = (const float*)d_in[17];
    const float* beta  = (const float*)d_in[18];

    float* out = (float*)d_out;

    float *hidden, *msg, *agg, *hn, *node, *cnt, *p1, *p3, *nfs, *zb;
    __nv_bfloat16 *wth, *wtl;
    cudaGetSymbolAddress((void**)&hidden, g_buf1);
    cudaGetSymbolAddress((void**)&msg,    g_msg);
    cudaGetSymbolAddress((void**)&agg,    g_agg);
    cudaGetSymbolAddress((void**)&hn,     g_hn);
    cudaGetSymbolAddress((void**)&node,   g_node);
    cudaGetSymbolAddress((void**)&cnt,    g_cnt);
    cudaGetSymbolAddress((void**)&p1,     g_p1);
    cudaGetSymbolAddress((void**)&p3,     g_p3);
    cudaGetSymbolAddress((void**)&nfs,    g_nfs);
    cudaGetSymbolAddress((void**)&zb,     g_zero256);
    cudaGetSymbolAddress((void**)&wth,    g_wth);
    cudaGetSymbolAddress((void**)&wtl,    g_wtl);

    __nv_bfloat16* hidh = (__nv_bfloat16*)hidden;
    __nv_bfloat16* hidl = hidh + (size_t)ME * Dn;
    __nv_bfloat16* msgh = (__nv_bfloat16*)msg;
    __nv_bfloat16* msgl = msgh + (size_t)ME * Dn;
    __nv_bfloat16* hnh  = (__nv_bfloat16*)hn;
    __nv_bfloat16* hnl  = hnh + (size_t)MN * Dn;
    __nv_bfloat16* nfh  = (__nv_bfloat16*)nfs;
    __nv_bfloat16* nfl  = nfh + (size_t)MN * Dn;

    cudaFuncSetAttribute(gemm_tc<5, false, true , false, true , 2>, cudaFuncAttributeMaxDynamicSharedMemorySize, SMEM_TOTAL);
    cudaFuncSetAttribute(gemm_tc<4, false, false, true , false, 1>, cudaFuncAttributeMaxDynamicSharedMemorySize, SMEM_TOTAL);
    cudaFuncSetAttribute(gemm_tc<1, false, true , true , false, 0>, cudaFuncAttributeMaxDynamicSharedMemorySize, SMEM_TOTAL);
    cudaFuncSetAttribute(gemm_tc<0, true , false, true , false, 0>, cudaFuncAttributeMaxDynamicSharedMemorySize, SMEM_TOTAL);
    cudaFuncSetAttribute(gemm_tc<0, false, true , true , false, 1>, cudaFuncAttributeMaxDynamicSharedMemorySize, SMEM_TOTAL);
    cudaFuncSetAttribute(gemm_tc<2, false, true , false, false, 0>, cudaFuncAttributeMaxDynamicSharedMemorySize, SMEM_TOTAL);
    cudaFuncSetAttribute(gemm_tc<3, false, true , false, false, 2>, cudaFuncAttributeMaxDynamicSharedMemorySize, SMEM_TOTAL);

    // zero scratch (plain memset nodes)
    cudaMemsetAsync(agg, 0, (size_t)MN * Dn * sizeof(float));
    cudaMemsetAsync(cnt, 0, (size_t)MN * sizeof(float));

    // weight transpose + bf16 split (head of PDL chain)
    WSrcs ws;
    ws.p[0] = tw1;          ws.p[1] = tw1 + 65536;  ws.p[2] = tw1 + 131072;
    ws.p[3] = tw2;          ws.p[4] = ew1;          ws.p[5] = ew2;
    ws.p[6] = nw1;          ws.p[7] = nw2;
    prep_weights_all<<<dim3(8, 8, 8), dim3(32, 8)>>>(ws, wth, wtl);

    launchP(split_pair, dim3((MN * Dn / 4) / 256), dim3(256), 0,
            (const float4*)node_feat, (uint2*)nfh, (uint2*)nfl);
    launchP(prep_edges, dim3(ME / 256), dim3(256), 0, edge_index, edge_mask);

    dim3 ge(2, ME / 128);
    dim3 gn(2, MN / 128);
    dim3 gn2(2, MN / 128, 2);
    // P1/P3 (WPOS=2: no wait — overlaps prep_edges' tail entirely)
    launchP(gemm_tc<5, false, true , false, true , 2>, gn2, dim3(256), (size_t)SMEM_TOTAL,
            (const float*)nullptr, (const __nv_bfloat16*)nfh, (const __nv_bfloat16*)nfl,
            (const __nv_bfloat16*)(wth + OW_T1A), (const __nv_bfloat16*)(wtl + OW_T1A),
            (const __nv_bfloat16*)(wth + OW_T1C), (const __nv_bfloat16*)(wtl + OW_T1C),
            (const float*)zb, (const float*)nullptr, p1, p3,
            (__nv_bfloat16*)nullptr, (__nv_bfloat16*)nullptr);
    // triplet layer1 (WPOS=1: A=edge_feat const; mainloop overlaps gemm5 tail)
    launchP(gemm_tc<4, false, false, true , false, 1>, ge, dim3(256), (size_t)SMEM_TOTAL,
            edge_feat, (const __nv_bfloat16*)nullptr, (const __nv_bfloat16*)nullptr,
            (const __nv_bfloat16*)(wth + OW_T1B), (const __nv_bfloat16*)(wtl + OW_T1B),
            (const __nv_bfloat16*)nullptr, (const __nv_bfloat16*)nullptr,
            tb1, (const float*)nullptr, (float*)nullptr, (float*)nullptr, hidh, hidl);
    // msg = (hidden@tw2+tb2)*mask (WPOS=0: A dependent)
    launchP(gemm_tc<1, false, true , true , false, 0>, ge, dim3(256), (size_t)SMEM_TOTAL,
            (const float*)nullptr, (const __nv_bfloat16*)hidh, (const __nv_bfloat16*)hidl,
            (const __nv_bfloat16*)(wth + OW_TW2), (const __nv_bfloat16*)(wtl + OW_TW2),
            (const __nv_bfloat16*)nullptr, (const __nv_bfloat16*)nullptr,
            tb2, (const float*)nullptr, (float*)nullptr, (float*)nullptr, msgh, msgl);
    // invc + node mask (needs cnt + msg atomics complete)
    launchP(prep_nodes, dim3(MN / 256), dim3(256), 0, node_mask, edge_mask);
    // node layer1 on agg*invc -> hn pair (WPOS=0; moved before edge-l1)
    launchP(gemm_tc<0, true , false, true , false, 0>, gn, dim3(256), (size_t)SMEM_TOTAL,
            (const float*)agg, (const __nv_bfloat16*)nullptr, (const __nv_bfloat16*)nullptr,
            (const __nv_bfloat16*)(wth + OW_NW1), (const __nv_bfloat16*)(wtl + OW_NW1),
            (const __nv_bfloat16*)nullptr, (const __nv_bfloat16*)nullptr,
            nb1, (const float*)nullptr, (float*)nullptr, (float*)nullptr, hnh, hnl);
    // edge update layer1 (WPOS=1: A=msg ready transitively; overlaps node-l1)
    launchP(gemm_tc<0, false, true , true , false, 1>, ge, dim3(256), (size_t)SMEM_TOTAL,
            (const float*)nullptr, (const __nv_bfloat16*)msgh, (const __nv_bfloat16*)msgl,
            (const __nv_bfloat16*)(wth + OW_EW1), (const __nv_bfloat16*)(wtl + OW_EW1),
            (const __nv_bfloat16*)nullptr, (const __nv_bfloat16*)nullptr,
            eb1, (const float*)nullptr, (float*)nullptr, (float*)nullptr, hidh, hidl);
    // edge_out = edge_feat + layer2 (WPOS=0: A dependent)
    launchP(gemm_tc<2, false, true , false, false, 0>, ge, dim3(256), (size_t)SMEM_TOTAL,
            (const float*)nullptr, (const __nv_bfloat16*)hidh, (const __nv_bfloat16*)hidl,
            (const __nv_bfloat16*)(wth + OW_EW2), (const __nv_bfloat16*)(wtl + OW_EW2),
            (const __nv_bfloat16*)nullptr, (const __nv_bfloat16*)nullptr,
            eb2, edge_feat, out + (size_t)MN * Dn, (float*)nullptr,
            (__nv_bfloat16*)nullptr, (__nv_bfloat16*)nullptr);
    // node layer2 (WPOS=2: A=hn + masks ready transitively; hides in edge_out tail)
    launchP(gemm_tc<3, false, true , false, false, 2>, gn, dim3(256), (size_t)SMEM_TOTAL,
            (const float*)nullptr, (const __nv_bfloat16*)hnh, (const __nv_bfloat16*)hnl,
            (const __nv_bfloat16*)(wth + OW_NW2), (const __nv_bfloat16*)(wtl + OW_NW2),
            (const __nv_bfloat16*)nullptr, (const __nv_bfloat16*)nullptr,
            nb2, node_feat, node, (float*)nullptr,
            (__nv_bfloat16*)nullptr, (__nv_bfloat16*)nullptr);
    // layernorm (waits for gemm3 completion)
    launchP(ln_kernel, dim3(MN), dim3(64), 0, (const float*)node, gamma, beta, out);
}

// round 17
// speedup vs baseline: 1.2430x; 1.2323x over previous
#include <cuda_runtime.h>
#include <cuda_fp16.h>
#include <cstdint>
#include <math.h>

// Problem constants
#define Bn 16
#define Nn 1024
#define En 16384
#define Dn 256
constexpr int ME = Bn * En;   // 262144 edge rows
constexpr int MN = Bn * Nn;   // 16384 node rows

// ============================ PTX helpers ===================================
__device__ __forceinline__ uint32_t smem_u32(const void* p) {
    uint32_t a;
    asm("{ .reg .u64 t; cvta.to.shared.u64 t, %1; cvt.u32.u64 %0, t; }"
        : "=r"(a) : "l"(p));
    return a;
}

#define LDSM4(r, addr) \
    asm volatile("ldmatrix.sync.aligned.m8n8.x4.shared.b16 {%0,%1,%2,%3}, [%4];" \
        : "=r"((r)[0]), "=r"((r)[1]), "=r"((r)[2]), "=r"((r)[3]) : "r"(addr))

#define MMA_FP16(d, a, b) \
    asm volatile("mma.sync.aligned.m16n8k16.row.col.f32.f16.f16.f32 " \
        "{%0,%1,%2,%3}, {%4,%5,%6,%7}, {%8,%9}, {%0,%1,%2,%3};" \
        : "+f"((d)[0]), "+f"((d)[1]), "+f"((d)[2]), "+f"((d)[3]) \
        : "r"((a)[0]), "r"((a)[1]), "r"((a)[2]), "r"((a)[3]), \
          "r"((b)[0]), "r"((b)[1]))

#define CP_ASYNC16(dst, src) \
    asm volatile("cp.async.cg.shared.global [%0], [%1], 16;" :: "r"(dst), "l"(src))
#define CP_COMMIT asm volatile("cp.async.commit_group;" ::: "memory")
#define CP_WAIT0  asm volatile("cp.async.wait_group 0;" ::: "memory")

#define RED_ADD_V2(p, a, b) \
    asm volatile("red.global.add.v2.f32 [%0], {%1,%2};" :: "l"(p), "f"(a), "f"(b) : "memory")

// Programmatic Dependent Launch (sm_90 PTX)
#define GDC_WAIT   asm volatile("griddepcontrol.wait;" ::: "memory")
#define GDC_LAUNCH asm volatile("griddepcontrol.launch_dependents;" ::: "memory")

#define SW128(x) ((x) ^ (((x) >> 3) & 0x70))

// ============================ scratch globals ================================
__device__ float g_buf1[(size_t)ME * Dn];   // hidden (fp16 hi/lo pair alias)
__device__ float g_msg [(size_t)ME * Dn];   // msg    (fp16 hi/lo pair alias)
__device__ float g_agg [(size_t)MN * Dn];   // fp32 (atomics)
__device__ float g_hn  [(size_t)MN * Dn];   // hn     (fp16 hi/lo pair alias)
__device__ float g_node[(size_t)MN * Dn];   // fp32 pre-LN
__device__ float g_p1  [(size_t)MN * Dn];   // node_feat @ W1a (fp32)
__device__ float g_p3  [(size_t)MN * Dn];   // node_feat @ W1c (fp32)
__device__ float g_nfs [(size_t)MN * Dn];   // node_feat pre-split (fp16 pair)
__device__ float g_cnt [MN];
__device__ float g_invc[MN];
__device__ int   g_srcrow[ME];
__device__ int   g_dstrow[ME];
__device__ float g_maskf [ME];
__device__ float g_nmaskf[MN];
__device__ float g_zero256[256];
// pre-transposed fp16 weights (hi only), 8 matrices of [256][256]
__device__ __half g_wth[524288];
constexpr size_t OW_T1A = 0,      OW_T1B = 65536,  OW_T1C = 131072,
                 OW_TW2 = 196608, OW_EW1 = 262144, OW_EW2 = 327680,
                 OW_NW1 = 393216, OW_NW2 = 458752;

__device__ __forceinline__ float silu_f(float x) { return x / (1.0f + __expf(-x)); }

// mask dtype: 0=float32, 1=uint8, 2=int32
__device__ __forceinline__ int sniff_dt(const unsigned int* m) {
    bool big = false, up = false;
    #pragma unroll
    for (int i = 0; i < 16; i++) {
        unsigned int w = m[i];
        unsigned char b0 = w & 0xff, b1 = (w >> 8) & 0xff,
                      b2 = (w >> 16) & 0xff, b3 = (w >> 24) & 0xff;
        if (b0 >= 2 || b1 >= 2 || b2 >= 2 || b3 >= 2) big = true;
        if (b1 | b2 | b3) up = true;
    }
    return big ? 0 : (up ? 1 : 2);
}

__device__ __forceinline__ float read_mask(const void* p, int i, int dt) {
    if (dt == 0) return ((const float*)p)[i];
    if (dt == 1) return ((const unsigned char*)p)[i] ? 1.0f : 0.0f;
    return ((const int*)p)[i] ? 1.0f : 0.0f;
}

// fp32x4 -> fp16 hi + fp16 lo (A exactly representable to ~2^-22)
__device__ __forceinline__ void split_f16x4(float4 v, uint2& hi, uint2& lo) {
    __half2 h01 = __floats2half2_rn(v.x, v.y);
    __half2 h23 = __floats2half2_rn(v.z, v.w);
    float2 f01 = __half22float2(h01);
    float2 f23 = __half22float2(h23);
    __half2 l01 = __floats2half2_rn(v.x - f01.x, v.y - f01.y);
    __half2 l23 = __floats2half2_rn(v.z - f23.x, v.w - f23.y);
    hi.x = *(uint32_t*)&h01; hi.y = *(uint32_t*)&h23;
    lo.x = *(uint32_t*)&l01; lo.y = *(uint32_t*)&l23;
}

// ---------------- small prep kernels (launch_dependents AFTER writes) --------
__global__ void prep_edges(const int* __restrict__ edge_index,
                           const void* __restrict__ edge_mask) {
    __shared__ int sdt;
    GDC_WAIT;
    if (threadIdx.x == 0) sdt = sniff_dt((const unsigned int*)edge_mask);
    __syncthreads();
    int dt = sdt;
    int r = blockIdx.x * blockDim.x + threadIdx.x;
    if (r < ME) {
        int b = r >> 14;
        int e = r & (En - 1);
        int src = edge_index[(size_t)b * 2 * En + e];
        int dst = edge_index[(size_t)b * 2 * En + En + e];
        float m = (read_mask(edge_mask, r, dt) != 0.0f) ? 1.0f : 0.0f;
        g_srcrow[r] = b * Nn + src;
        g_dstrow[r] = b * Nn + dst;
        g_maskf[r]  = m;
        if (m != 0.0f) atomicAdd(&g_cnt[b * Nn + dst], 1.0f);
    }
    GDC_LAUNCH;
}

__global__ void prep_nodes(const void* __restrict__ node_mask,
                           const void* __restrict__ edge_mask) {
    __shared__ int sdt;
    GDC_WAIT;
    if (threadIdx.x == 0) sdt = sniff_dt((const unsigned int*)edge_mask);
    __syncthreads();
    int dt = sdt;
    int v = blockIdx.x * blockDim.x + threadIdx.x;
    if (v < MN) {
        g_invc[v]   = 1.0f / fmaxf(g_cnt[v], 1.0f);
        g_nmaskf[v] = (read_mask(node_mask, v, dt) != 0.0f) ? 1.0f : 0.0f;
    }
    GDC_LAUNCH;
}

// elementwise fp32 -> fp16 hi/lo pair split (node_feat)
__global__ void split_pair(const float4* __restrict__ src,
                           uint2* __restrict__ dsth, uint2* __restrict__ dstl) {
    GDC_WAIT;
    int i = blockIdx.x * blockDim.x + threadIdx.x;
    uint2 hi, lo;
    split_f16x4(src[i], hi, lo);
    dsth[i] = hi;
    dstl[i] = lo;
    GDC_LAUNCH;
}

// All 8 weight transposes in one launch; smem-tile coalesced; fp16 hi only.
struct WSrcs { const float* p[8]; };
__global__ void prep_weights_all(WSrcs srcs, __half* __restrict__ wth) {
    __shared__ float tile[32][33];
    const float* src = srcs.p[blockIdx.z];
    int kt = blockIdx.x * 32, nt = blockIdx.y * 32;
    #pragma unroll
    for (int i = threadIdx.y; i < 32; i += 8)
        tile[i][threadIdx.x] = src[(size_t)(kt + i) * 256 + nt + threadIdx.x];
    __syncthreads();
    size_t base = (size_t)blockIdx.z * 65536;
    #pragma unroll
    for (int i = threadIdx.y; i < 32; i += 8) {
        int n = nt + i, k = kt + threadIdx.x;
        wth[base + (size_t)n * 256 + k] = __float2half_rn(tile[threadIdx.x][i]);
    }
    GDC_LAUNCH;
}

// ============================ tensor-core GEMM (mma.sync) ====================
// out[M,256] = A[M,256] @ W[256,256] via fp16x2: (Ahi+Alo) @ Bhi.
// A split exactly into fp16 hi/lo (error 2^-22); only B's fp16 rounding
// (~2^-12 RMS) remains -> per-GEMM rel err ~1.5e-4.
// Block tile 128x128, 8 warps (2M x 4N), warp tile 64x32; 32 MMAs / k-chunk.
// A double-buffered, B(hi) single-buffered. occupancy 2 (84KB smem).
// WPOS: 0 = wait before mainloop; 1 = wait after mainloop; 2 = no wait.

constexpr int SM_BIAS  = 0;      // 128 f32
constexpr int SM_SCALE = 512;    // 128 f32
constexpr int SM_AH    = 1024;   // [2][16384]
constexpr int SM_AL    = 33792;  // [2][16384]
constexpr int SM_BH    = 66560;  // [16384]
constexpr int SMEM_TOTAL = 83968;

__device__ __forceinline__ void store_pair(__half* outh, __half* outl,
                                           size_t o, float a, float b) {
    __half2 h = __floats2half2_rn(a, b);
    float2 hf = __half22float2(h);
    __half2 l = __floats2half2_rn(a - hf.x, b - hf.y);
    *(__half2*)&outh[o] = h;
    *(__half2*)&outl[o] = l;
}

template<int MODE, bool SCALE, bool AF16, bool OF16, bool DUAL, int WPOS>
__global__ void __launch_bounds__(256, 2)
gemm_tc(const float* __restrict__ A,                 // fp32 A (when !AF16)
        const __half* __restrict__ Ah,               // fp16 A pair (when AF16)
        const __half* __restrict__ Al,
        const __half* WTh,                           // [256][256] fp16 hi
        const __half* WTh2,                          // DUAL second set
        const float* __restrict__ bias,
        const float* __restrict__ residual,
        float* out,
        float* out2,
        __half* __restrict__ outh,
        __half* __restrict__ outl) {
    extern __shared__ __align__(1024) char sm[];
    const uint32_t smb = smem_u32(sm);
    const int tid  = threadIdx.x;
    const int wid  = tid >> 5;
    const int lane = tid & 31;
    const int row0 = blockIdx.y * 128;
    const int col0 = blockIdx.x * 128;
    const int wm = (wid & 1) * 64;
    const int wn = (wid >> 1) * 32;

    if (DUAL && blockIdx.z == 1) { WTh = WTh2; out = out2; }

    // ---- pre-wait prologue: const / transitively-ready data ----
    if (tid < 128) ((float*)(sm + SM_BIAS))[tid] = bias[col0 + tid];

    const int grp = lane >> 3, lr = lane & 7;
    const uint32_t kadd = (grp >> 1) * 16;
    uint32_t saA[4], xaA[4], saB[2], xaB[2];
    #pragma unroll
    for (int mi = 0; mi < 4; mi++) {
        int r = wm + mi * 16 + (grp & 1) * 8 + lr;
        saA[mi] = (uint32_t)r * 128;
        xaA[mi] = (uint32_t)(r & 7) << 4;
    }
    #pragma unroll
    for (int nj = 0; nj < 2; nj++) {
        int r = wn + nj * 16 + (grp & 1) * 8 + lr;
        saB[nj] = (uint32_t)r * 128;
        xaB[nj] = (uint32_t)(r & 7) << 4;
    }

    auto cpB = [&](int k0) {
        uint32_t bh = smb + SM_BH;
        #pragma unroll
        for (int i = 0; i < 4; i++) {
            int idx = tid + i * 256;
            int n = idx >> 3, j = idx & 7;
            uint32_t boff = SW128((uint32_t)(n * 128 + j * 16));
            CP_ASYNC16(bh + boff, WTh + (size_t)(col0 + n) * Dn + k0 + j * 8);
        }
    };
    cpB(0);

    if (WPOS == 0) {
        GDC_WAIT;
        if (SCALE && tid < 128) ((float*)(sm + SM_SCALE))[tid] = g_invc[row0 + tid];
    }
    __syncthreads();

    const float* s_scale = (const float*)(sm + SM_SCALE);
    float acc[4][4][4] = {};

    auto ldsplitA = [&](int k0, int buf) {
        char* ah = sm + SM_AH + buf * 16384;
        char* al = sm + SM_AL + buf * 16384;
        float4 pa[4][2];
        #pragma unroll
        for (int i = 0; i < 4; i++) {
            int idx = tid + i * 256;
            int ar = idx >> 3;
            int c8 = (idx & 7) * 8;
            size_t off = (size_t)(row0 + ar) * Dn + k0 + c8;
            pa[i][0] = *(const float4*)&A[off];
            pa[i][1] = *(const float4*)&A[off + 4];
        }
        #pragma unroll
        for (int i = 0; i < 4; i++) {
            int idx = tid + i * 256;
            int ar = idx >> 3;
            int c8 = (idx & 7) * 8;
            float4 v0 = pa[i][0], v1 = pa[i][1];
            if (SCALE) {
                float s = s_scale[ar];
                v0.x *= s; v0.y *= s; v0.z *= s; v0.w *= s;
                v1.x *= s; v1.y *= s; v1.z *= s; v1.w *= s;
            }
            uint2 h0, l0, h1, l1;
            split_f16x4(v0, h0, l0);
            split_f16x4(v1, h1, l1);
            uint32_t boff = SW128((uint32_t)(ar * 128 + c8 * 2));
            *(uint4*)(ah + boff) = make_uint4(h0.x, h0.y, h1.x, h1.y);
            *(uint4*)(al + boff) = make_uint4(l0.x, l0.y, l1.x, l1.y);
        }
    };
    auto cpA = [&](int k0, int buf) {
        uint32_t ah = smb + SM_AH + buf * 16384;
        uint32_t al = smb + SM_AL + buf * 16384;
        #pragma unroll
        for (int i = 0; i < 4; i++) {
            int idx = tid + i * 256;
            int r = idx >> 3, j = idx & 7;
            uint32_t boff = SW128((uint32_t)(r * 128 + j * 16));
            size_t go = (size_t)(row0 + r) * Dn + k0 + j * 8;
            CP_ASYNC16(ah + boff, Ah + go);
            CP_ASYNC16(al + boff, Al + go);
        }
    };
    auto compute = [&](int buf) {
        uint32_t abh = smb + SM_AH + buf * 16384;
        uint32_t abl = smb + SM_AL + buf * 16384;
        uint32_t bbh = smb + SM_BH;
        #pragma unroll
        for (int ks = 0; ks < 4; ks++) {
            uint32_t kx = ks * 32 + kadd;
            uint32_t ahi[4][4], alo[4][4], bhi[4][2];
            #pragma unroll
            for (int mi = 0; mi < 4; mi++) {
                LDSM4(ahi[mi], abh + saA[mi] + (kx ^ xaA[mi]));
                LDSM4(alo[mi], abl + saA[mi] + (kx ^ xaA[mi]));
            }
            #pragma unroll
            for (int nj = 0; nj < 2; nj++) {
                uint32_t r[4];
                LDSM4(r, bbh + saB[nj] + (kx ^ xaB[nj]));
                bhi[nj * 2][0] = r[0]; bhi[nj * 2 + 1][0] = r[1];
                bhi[nj * 2][1] = r[2]; bhi[nj * 2 + 1][1] = r[3];
            }
            #pragma unroll
            for (int mi = 0; mi < 4; mi++)
                #pragma unroll
                for (int ni = 0; ni < 4; ni++)
                    MMA_FP16(acc[mi][ni], ahi[mi], bhi[ni]);
            #pragma unroll
            for (int mi = 0; mi < 4; mi++)
                #pragma unroll
                for (int ni = 0; ni < 4; ni++)
                    MMA_FP16(acc[mi][ni], alo[mi], bhi[ni]);
        }
    };

    constexpr int nT = 4;   // K = 256 in chunks of 64
    if (AF16) cpA(0, 0); else ldsplitA(0, 0);
    CP_COMMIT;
    CP_WAIT0;
    __syncthreads();

    int buf = 0;
    for (int t = 0; t < nT; t++) {
        if (t + 1 < nT) {
            if (AF16) { cpA((t + 1) * 64, buf ^ 1); CP_COMMIT; }
            else ldsplitA((t + 1) * 64, buf ^ 1);
        }
        compute(buf);
        if (t + 1 < nT) {
            __syncthreads();             // all warps done reading B(t)
            cpB((t + 1) * 64);
            CP_COMMIT;
            CP_WAIT0;                    // A(t+1) + B(t+1) arrived
            __syncthreads();
            buf ^= 1;
        }
    }

    if (WPOS == 1) GDC_WAIT;   // epilogue inputs depend on predecessor
    GDC_LAUNCH;                // successors may start; tail wave backfilled

    // ---- epilogue ---------------------------------------------------------
    const float* sb = (const float*)(sm + SM_BIAS);
    #pragma unroll
    for (int mi = 0; mi < 4; mi++) {
        int r0g = row0 + wm + mi * 16 + (lane >> 2);
        int r1g = r0g + 8;
        float mk0 = 1.0f, mk1 = 1.0f;
        int dr0 = 0, dr1 = 0, sr0 = 0, sr1 = 0;
        if (MODE == 1) {
            mk0 = g_maskf[r0g]; dr0 = g_dstrow[r0g];
            mk1 = g_maskf[r1g]; dr1 = g_dstrow[r1g];
        } else if (MODE == 3) {
            mk0 = g_nmaskf[r0g];
            mk1 = g_nmaskf[r1g];
        } else if (MODE == 4) {
            sr0 = g_srcrow[r0g]; dr0 = g_dstrow[r0g];
            sr1 = g_srcrow[r1g]; dr1 = g_dstrow[r1g];
        }
        #pragma unroll
        for (int ni = 0; ni < 4; ni++) {
            int cl = wn + ni * 8 + (lane & 3) * 2;
            int cg = col0 + cl;
            float b0 = sb[cl], b1 = sb[cl + 1];
            float v00 = acc[mi][ni][0] + b0, v01 = acc[mi][ni][1] + b1;
            float v10 = acc[mi][ni][2] + b0, v11 = acc[mi][ni][3] + b1;
            size_t o0 = (size_t)r0g * Dn + cg;
            size_t o1 = (size_t)r1g * Dn + cg;
            if (MODE == 0) {
                v00 = silu_f(v00); v01 = silu_f(v01);
                v10 = silu_f(v10); v11 = silu_f(v11);
            } else if (MODE == 1) {
                v00 *= mk0; v01 *= mk0; v10 *= mk1; v11 *= mk1;
                if (mk0 != 0.0f) RED_ADD_V2(&g_agg[(size_t)dr0 * Dn + cg], v00, v01);
                if (mk1 != 0.0f) RED_ADD_V2(&g_agg[(size_t)dr1 * Dn + cg], v10, v11);
            } else if (MODE == 2) {
                float2 q0 = *(const float2*)&residual[o0];
                float2 q1 = *(const float2*)&residual[o1];
                v00 += q0.x; v01 += q0.y; v10 += q1.x; v11 += q1.y;
            } else if (MODE == 3) {
                float2 q0 = *(const float2*)&residual[o0];
                float2 q1 = *(const float2*)&residual[o1];
                v00 = q0.x + v00 * mk0; v01 = q0.y + v01 * mk0;
                v10 = q1.x + v10 * mk1; v11 = q1.y + v11 * mk1;
            } else if (MODE == 4) {
                float2 p0 = *(const float2*)&g_p1[(size_t)sr0 * Dn + cg];
                float2 p1 = *(const float2*)&g_p1[(size_t)sr1 * Dn + cg];
                float2 q0 = *(const float2*)&g_p3[(size_t)dr0 * Dn + cg];
                float2 q1 = *(const float2*)&g_p3[(size_t)dr1 * Dn + cg];
                v00 = silu_f(v00 + p0.x + q0.x); v01 = silu_f(v01 + p0.y + q0.y);
                v10 = silu_f(v10 + p1.x + q1.x); v11 = silu_f(v11 + p1.y + q1.y);
            }
            if (OF16) {
                store_pair(outh, outl, o0, v00, v01);
                store_pair(outh, outl, o1, v10, v11);
            } else {
                *(float2*)&out[o0] = make_float2(v00, v01);
                *(float2*)&out[o1] = make_float2(v10, v11);
            }
        }
    }
}

// ---------------- layernorm over last dim (256), float4 vectorized ----------
__global__ void ln_kernel(const float* __restrict__ x,
                          const float* __restrict__ gamma,
                          const float* __restrict__ beta,
                          float* __restrict__ out) {
    int v = blockIdx.x, t = threadIdx.x;   // 64 threads, 4 elems each
    float4 g = *(const float4*)&gamma[t * 4];
    float4 bb = *(const float4*)&beta[t * 4];
    GDC_WAIT;
    GDC_LAUNCH;
    float4 val = *(const float4*)&x[(size_t)v * Dn + t * 4];
    float s  = val.x + val.y + val.z + val.w;
    float s2 = val.x * val.x + val.y * val.y + val.z * val.z + val.w * val.w;
    #pragma unroll
    for (int o = 16; o > 0; o >>= 1) {
        s  += __shfl_xor_sync(0xffffffffu, s,  o);
        s2 += __shfl_xor_sync(0xffffffffu, s2, o);
    }
    __shared__ float ws[2], ws2[2];
    int w = t >> 5;
    if ((t & 31) == 0) { ws[w] = s; ws2[w] = s2; }
    __syncthreads();
    float sa  = ws[0] + ws[1];
    float sa2 = ws2[0] + ws2[1];
    float mean = sa * (1.0f / 256.0f);
    float var  = sa2 * (1.0f / 256.0f) - mean * mean;
    float inv  = rsqrtf(var + 1e-5f);
    float4 o;
    o.x = (val.x - mean) * inv * g.x + bb.x;
    o.y = (val.y - mean) * inv * g.y + bb.y;
    o.z = (val.z - mean) * inv * g.z + bb.z;
    o.w = (val.w - mean) * inv * g.w + bb.w;
    *(float4*)&out[(size_t)v * Dn + t * 4] = o;
}

// ---------------- PDL launch helper ------------------------------------------
template<typename F, typename... Args>
static void launchP(F f, dim3 g, dim3 b, size_t smem, Args... args) {
    cudaLaunchConfig_t cfg = {};
    cfg.gridDim = g;
    cfg.blockDim = b;
    cfg.dynamicSmemBytes = smem;
    cfg.stream = 0;
    cudaLaunchAttribute at;
    at.id = cudaLaunchAttributeProgrammaticStreamSerialization;
    at.val.programmaticStreamSerializationAllowed = 1;
    cfg.attrs = &at;
    cfg.numAttrs = 1;
    cudaLaunchKernelEx(&cfg, f, args...);
}

// ---------------- launch ------------------------------------------------------
extern "C" void kernel_launch(void* const* d_in, const int* in_sizes, int n_in,
                              void* d_out, int out_size) {
    const float* node_feat = (const float*)d_in[0];
    const float* edge_feat = (const float*)d_in[1];
    const int*   edge_index = (const int*)d_in[2];
    const void*  node_mask = d_in[3];
    const void*  edge_mask = d_in[4];
    const float* tw1 = (const float*)d_in[5];
    const float* tb1 = (const float*)d_in[6];
    const float* tw2 = (const float*)d_in[7];
    const float* tb2 = (const float*)d_in[8];
    const float* nw1 = (const float*)d_in[9];
    const float* nb1 = (const float*)d_in[10];
    const float* nw2 = (const float*)d_in[11];
    const float* nb2 = (const float*)d_in[12];
    const float* ew1 = (const float*)d_in[13];
    const float* eb1 = (const float*)d_in[14];
    const float* ew2 = (const float*)d_in[15];
    const float* eb2 = (const float*)d_in[16];
    const float* gamma = (const float*)d_in[17];
    const float* beta  = (const float*)d_in[18];

    float* out = (float*)d_out;

    float *hidden, *msg, *agg, *hn, *node, *cnt, *p1, *p3, *nfs, *zb;
    __half *wth;
    cudaGetSymbolAddress((void**)&hidden, g_buf1);
    cudaGetSymbolAddress((void**)&msg,    g_msg);
    cudaGetSymbolAddress((void**)&agg,    g_agg);
    cudaGetSymbolAddress((void**)&hn,     g_hn);
    cudaGetSymbolAddress((void**)&node,   g_node);
    cudaGetSymbolAddress((void**)&cnt,    g_cnt);
    cudaGetSymbolAddress((void**)&p1,     g_p1);
    cudaGetSymbolAddress((void**)&p3,     g_p3);
    cudaGetSymbolAddress((void**)&nfs,    g_nfs);
    cudaGetSymbolAddress((void**)&zb,     g_zero256);
    cudaGetSymbolAddress((void**)&wth,    g_wth);

    __half* hidh = (__half*)hidden;
    __half* hidl = hidh + (size_t)ME * Dn;
    __half* msgh = (__half*)msg;
    __half* msgl = msgh + (size_t)ME * Dn;
    __half* hnh  = (__half*)hn;
    __half* hnl  = hnh + (size_t)MN * Dn;
    __half* nfh  = (__half*)nfs;
    __half* nfl  = nfh + (size_t)MN * Dn;

    cudaFuncSetAttribute(gemm_tc<5, false, true , false, true , 2>, cudaFuncAttributeMaxDynamicSharedMemorySize, SMEM_TOTAL);
    cudaFuncSetAttribute(gemm_tc<4, false, false, true , false, 1>, cudaFuncAttributeMaxDynamicSharedMemorySize, SMEM_TOTAL);
    cudaFuncSetAttribute(gemm_tc<1, false, true , true , false, 0>, cudaFuncAttributeMaxDynamicSharedMemorySize, SMEM_TOTAL);
    cudaFuncSetAttribute(gemm_tc<0, true , false, true , false, 0>, cudaFuncAttributeMaxDynamicSharedMemorySize, SMEM_TOTAL);
    cudaFuncSetAttribute(gemm_tc<0, false, true , true , false, 1>, cudaFuncAttributeMaxDynamicSharedMemorySize, SMEM_TOTAL);
    cudaFuncSetAttribute(gemm_tc<2, false, true , false, false, 0>, cudaFuncAttributeMaxDynamicSharedMemorySize, SMEM_TOTAL);
    cudaFuncSetAttribute(gemm_tc<3, false, true , false, false, 2>, cudaFuncAttributeMaxDynamicSharedMemorySize, SMEM_TOTAL);

    // zero scratch (plain memset nodes)
    cudaMemsetAsync(agg, 0, (size_t)MN * Dn * sizeof(float));
    cudaMemsetAsync(cnt, 0, (size_t)MN * sizeof(float));

    // weight transpose + fp16 convert (head of PDL chain)
    WSrcs ws;
    ws.p[0] = tw1;          ws.p[1] = tw1 + 65536;  ws.p[2] = tw1 + 131072;
    ws.p[3] = tw2;          ws.p[4] = ew1;          ws.p[5] = ew2;
    ws.p[6] = nw1;          ws.p[7] = nw2;
    prep_weights_all<<<dim3(8, 8, 8), dim3(32, 8)>>>(ws, wth);

    launchP(split_pair, dim3((MN * Dn / 4) / 256), dim3(256), 0,
            (const float4*)node_feat, (uint2*)nfh, (uint2*)nfl);
    launchP(prep_edges, dim3(ME / 256), dim3(256), 0, edge_index, edge_mask);

    dim3 ge(2, ME / 128);
    dim3 gn(2, MN / 128);
    dim3 gn2(2, MN / 128, 2);
    // P1/P3 (WPOS=2: no wait — overlaps prep_edges entirely)
    launchP(gemm_tc<5, false, true , false, true , 2>, gn2, dim3(256), (size_t)SMEM_TOTAL,
            (const float*)nullptr, (const __half*)nfh, (const __half*)nfl,
            (const __half*)(wth + OW_T1A), (const __half*)(wth + OW_T1C),
            (const float*)zb, (const float*)nullptr, p1, p3,
            (__half*)nullptr, (__half*)nullptr);
    // triplet layer1 (WPOS=1: A=edge_feat const; mainloop overlaps gemm5 tail)
    launchP(gemm_tc<4, false, false, true , false, 1>, ge, dim3(256), (size_t)SMEM_TOTAL,
            edge_feat, (const __half*)nullptr, (const __half*)nullptr,
            (const __half*)(wth + OW_T1B), (const __half*)nullptr,
            tb1, (const float*)nullptr, (float*)nullptr, (float*)nullptr, hidh, hidl);
    // msg = (hidden@tw2+tb2)*mask (WPOS=0: A dependent)
    launchP(gemm_tc<1, false, true , true , false, 0>, ge, dim3(256), (size_t)SMEM_TOTAL,
            (const float*)nullptr, (const __half*)hidh, (const __half*)hidl,
            (const __half*)(wth + OW_TW2), (const __half*)nullptr,
            tb2, (const float*)nullptr, (float*)nullptr, (float*)nullptr, msgh, msgl);
    // invc + node mask (needs cnt + msg atomics complete)
    launchP(prep_nodes, dim3(MN / 256), dim3(256), 0, node_mask, edge_mask);
    // node layer1 on agg*invc -> hn pair (WPOS=0)
    launchP(gemm_tc<0, true , false, true , false, 0>, gn, dim3(256), (size_t)SMEM_TOTAL,
            (const float*)agg, (const __half*)nullptr, (const __half*)nullptr,
            (const __half*)(wth + OW_NW1), (const __half*)nullptr,
            nb1, (const float*)nullptr, (float*)nullptr, (float*)nullptr, hnh, hnl);
    // edge update layer1 (WPOS=1: A=msg ready transitively; overlaps node-l1)
    launchP(gemm_tc<0, false, true , true , false, 1>, ge, dim3(256), (size_t)SMEM_TOTAL,
            (const float*)nullptr, (const __half*)msgh, (const __half*)msgl,
            (const __half*)(wth + OW_EW1), (const __half*)nullptr,
            eb1, (const float*)nullptr, (float*)nullptr, (float*)nullptr, hidh, hidl);
    // edge_out = edge_feat + layer2 (WPOS=0: A dependent)
    launchP(gemm_tc<2, false, true , false, false, 0>, ge, dim3(256), (size_t)SMEM_TOTAL,
            (const float*)nullptr, (const __half*)hidh, (const __half*)hidl,
            (const __half*)(wth + OW_EW2), (const __half*)nullptr,
            eb2, edge_feat, out + (size_t)MN * Dn, (float*)nullptr,
            (__half*)nullptr, (__half*)nullptr);
    // node layer2 (WPOS=2: A=hn + masks ready transitively; hides in edge_out tail)
    launchP(gemm_tc<3, false, true , false, false, 2>, gn, dim3(256), (size_t)SMEM_TOTAL,
            (const float*)nullptr, (const __half*)hnh, (const __half*)hnl,
            (const __half*)(wth + OW_NW2), (const __half*)nullptr,
            nb2, node_feat, node, (float*)nullptr,
            (__half*)nullptr, (__half*)nullptr);
    // layernorm (waits for gemm3 completion)
    launchP(ln_kernel, dim3(MN), dim3(64), 0, (const float*)node, gamma, beta, out);
}